// round 1
// baseline (speedup 1.0000x reference)
#include <cuda_runtime.h>
#include <math.h>

// ---------------------------------------------------------------------------
// PoincareEmbHingeLoss  (B=4096, C=10000, D=64, fp32)
// loss = (sum_{b,c} relu(d2c[b] - d2w[b,c] + 0.1) - 0.1*B) / B
// d2w computed via fused tiled GEMM (pred @ all^T) + arccosh epilogue.
// ---------------------------------------------------------------------------

#define D_DIM 64
#define BM 128
#define BN 64
#define TM 8
#define TN 4
#define NTHREADS 256
#define MARGIN 0.1f
#define BOUNDARY_EPS 1e-5f
#define ACOSH_EPS 1e-7f

#define MAX_B 4096
#define MAX_C 10048
#define MAX_PARTIALS 8192

__device__ float  g_row_pn[MAX_B];    // clamped ||p||^2
__device__ float  g_row_s[MAX_B];     // 2 / (1 - pn)
__device__ float  g_row_d2c[MAX_B];   // arccosh dist to correct target
__device__ float  g_col_an[MAX_C];    // clamped ||a||^2
__device__ float  g_col_ia[MAX_C];    // 1 / (1 - an)
__device__ double g_partials[MAX_PARTIALS];

// ---------------------------------------------------------------------------
// Per-row precompute: pn, 2/(1-pn), dist2correct (fp64 for the scalar path)
// ---------------------------------------------------------------------------
__global__ void row_precompute_kernel(const float* __restrict__ pred,
                                      const float* __restrict__ targ,
                                      int B) {
    int r = blockIdx.x * blockDim.x + threadIdx.x;
    if (r >= B) return;
    const float4* p4 = (const float4*)(pred + (size_t)r * D_DIM);
    const float4* t4 = (const float4*)(targ + (size_t)r * D_DIM);
    float pn = 0.f, tn = 0.f, sc = 0.f;
#pragma unroll
    for (int i = 0; i < D_DIM / 4; i++) {
        float4 p = p4[i];
        float4 t = t4[i];
        pn += p.x * p.x + p.y * p.y + p.z * p.z + p.w * p.w;
        tn += t.x * t.x + t.y * t.y + t.z * t.z + t.w * t.w;
        float dx = p.x - t.x, dy = p.y - t.y, dz = p.z - t.z, dw = p.w - t.w;
        sc += dx * dx + dy * dy + dz * dz + dw * dw;
    }
    pn = fminf(fmaxf(pn, 0.f), 1.f - BOUNDARY_EPS);
    tn = fminf(fmaxf(tn, 0.f), 1.f - BOUNDARY_EPS);
    double x = 1.0 + 2.0 * (double)sc / ((1.0 - (double)pn) * (1.0 - (double)tn));
    double xm = 1.0 + (double)ACOSH_EPS;
    if (x < xm) x = xm;
    double d2c = log(x + sqrt(x * x - 1.0));
    g_row_pn[r] = pn;
    g_row_s[r] = 2.f / (1.f - pn);
    g_row_d2c[r] = (float)d2c;
}

// ---------------------------------------------------------------------------
// Per-col precompute: an, 1/(1-an)
// ---------------------------------------------------------------------------
__global__ void col_precompute_kernel(const float* __restrict__ all, int C) {
    int c = blockIdx.x * blockDim.x + threadIdx.x;
    if (c >= C) return;
    const float4* a4 = (const float4*)(all + (size_t)c * D_DIM);
    float an = 0.f;
#pragma unroll
    for (int i = 0; i < D_DIM / 4; i++) {
        float4 a = a4[i];
        an += a.x * a.x + a.y * a.y + a.z * a.z + a.w * a.w;
    }
    an = fminf(fmaxf(an, 0.f), 1.f - BOUNDARY_EPS);
    g_col_an[c] = an;
    g_col_ia[c] = 1.f / (1.f - an);
}

// ---------------------------------------------------------------------------
// Fused tiled GEMM + arccosh + hinge epilogue.
// Tile: BM=128 rows (pred) x BN=64 cols (all), full K=D=64 in smem.
// 256 threads, each owns TM=8 x TN=4 outputs.
// ---------------------------------------------------------------------------
__global__ __launch_bounds__(NTHREADS)
void fused_hinge_kernel(const float* __restrict__ pred,
                        const float* __restrict__ all,
                        int B, int C) {
    __shared__ float As[D_DIM][BM];   // 32 KB, [k][m]
    __shared__ float Bs[D_DIM][BN];   // 16 KB, [k][n]

    const int tid = threadIdx.x;
    const int m0 = blockIdx.y * BM;
    const int n0 = blockIdx.x * BN;

    // Load A tile (transposed): BM rows x 16 float4 = 2048 f4, 8 per thread.
#pragma unroll
    for (int i = 0; i < (BM * (D_DIM / 4)) / NTHREADS; i++) {
        int id = tid + i * NTHREADS;
        int r = id >> 4;            // row within tile
        int c4 = id & 15;           // float4 index along k
        int row = m0 + r;
        if (row >= B) row = B - 1;  // clamp; masked in epilogue
        float4 v = ((const float4*)(pred + (size_t)row * D_DIM))[c4];
        As[c4 * 4 + 0][r] = v.x;
        As[c4 * 4 + 1][r] = v.y;
        As[c4 * 4 + 2][r] = v.z;
        As[c4 * 4 + 3][r] = v.w;
    }
    // Load B tile (transposed): BN rows x 16 float4 = 1024 f4, 4 per thread.
#pragma unroll
    for (int i = 0; i < (BN * (D_DIM / 4)) / NTHREADS; i++) {
        int id = tid + i * NTHREADS;
        int r = id >> 4;
        int c4 = id & 15;
        int col = n0 + r;
        if (col >= C) col = C - 1;  // clamp; masked in epilogue
        float4 v = ((const float4*)(all + (size_t)col * D_DIM))[c4];
        Bs[c4 * 4 + 0][r] = v.x;
        Bs[c4 * 4 + 1][r] = v.y;
        Bs[c4 * 4 + 2][r] = v.z;
        Bs[c4 * 4 + 3][r] = v.w;
    }
    __syncthreads();

    const int tx = tid & 15;   // 16 col-groups of TN=4  -> 64 cols
    const int ty = tid >> 4;   // 16 row-groups of TM=8  -> 128 rows

    float acc[TM][TN];
#pragma unroll
    for (int i = 0; i < TM; i++)
#pragma unroll
        for (int j = 0; j < TN; j++) acc[i][j] = 0.f;

#pragma unroll 8
    for (int k = 0; k < D_DIM; k++) {
        float4 a0 = *(const float4*)&As[k][ty * TM];
        float4 a1 = *(const float4*)&As[k][ty * TM + 4];
        float4 bb = *(const float4*)&Bs[k][tx * TN];
        float a[TM] = {a0.x, a0.y, a0.z, a0.w, a1.x, a1.y, a1.z, a1.w};
        float b[TN] = {bb.x, bb.y, bb.z, bb.w};
#pragma unroll
        for (int i = 0; i < TM; i++)
#pragma unroll
            for (int j = 0; j < TN; j++)
                acc[i][j] = fmaf(a[i], b[j], acc[i][j]);
    }

    // ---- Epilogue: arccosh distance + hinge, accumulate per-thread ----
    float rp[TM], rs[TM], rd[TM];
#pragma unroll
    for (int i = 0; i < TM; i++) {
        int row = m0 + ty * TM + i;
        int rr = row < B ? row : B - 1;
        rp[i] = g_row_pn[rr];
        rs[i] = g_row_s[rr];
        rd[i] = g_row_d2c[rr];
    }

    float tsum = 0.f;
#pragma unroll
    for (int j = 0; j < TN; j++) {
        int col = n0 + tx * TN + j;
        bool okc = (col < C);
        int cc = okc ? col : C - 1;
        float an = g_col_an[cc];
        float ia = g_col_ia[cc];
#pragma unroll
        for (int i = 0; i < TM; i++) {
            int row = m0 + ty * TM + i;
            bool ok = okc && (row < B);
            float sqd = fmaxf(rp[i] + an - 2.f * acc[i][j], 0.f);
            float t = fmaxf(sqd * rs[i] * ia, ACOSH_EPS);  // t = x - 1 >= eps
            // arccosh(1+t) = log(1 + t + sqrt(t*(t+2)))  (cancellation-free)
            float y = 1.f + t + __fsqrt_rn(fmaf(t, t, 2.f * t));
            float dw = __logf(y);
            float h = fmaxf(rd[i] - dw + MARGIN, 0.f);
            tsum += ok ? h : 0.f;
        }
    }

    // ---- Deterministic block reduction (reuse As smem) ----
    __syncthreads();
    float* red = &As[0][0];
    red[tid] = tsum;
    __syncthreads();
#pragma unroll
    for (int s = NTHREADS / 2; s > 0; s >>= 1) {
        if (tid < s) red[tid] += red[tid + s];
        __syncthreads();
    }
    if (tid == 0)
        g_partials[blockIdx.y * gridDim.x + blockIdx.x] = (double)red[0];
}

// ---------------------------------------------------------------------------
// Final fixed-order reduction -> loss
// ---------------------------------------------------------------------------
__global__ void finish_kernel(float* __restrict__ out, int nparts, int B) {
    __shared__ double red[NTHREADS];
    int tid = threadIdx.x;
    double s = 0.0;
    for (int i = tid; i < nparts; i += NTHREADS) s += g_partials[i];
    red[tid] = s;
    __syncthreads();
#pragma unroll
    for (int st = NTHREADS / 2; st > 0; st >>= 1) {
        if (tid < st) red[tid] += red[tid + st];
        __syncthreads();
    }
    if (tid == 0) {
        double hinge = red[0];
        out[0] = (float)((hinge - (double)MARGIN * (double)B) / (double)B);
    }
}

// ---------------------------------------------------------------------------
extern "C" void kernel_launch(void* const* d_in, const int* in_sizes, int n_in,
                              void* d_out, int out_size) {
    const float* pred = (const float*)d_in[0];
    const float* targ = (const float*)d_in[1];
    const float* all  = (const float*)d_in[2];
    float* out = (float*)d_out;

    int B = in_sizes[0] / D_DIM;   // 4096
    int C = in_sizes[2] / D_DIM;   // 10000

    row_precompute_kernel<<<(B + 255) / 256, 256>>>(pred, targ, B);
    col_precompute_kernel<<<(C + 255) / 256, 256>>>(all, C);

    dim3 grid((C + BN - 1) / BN, (B + BM - 1) / BM);   // (157, 32)
    fused_hinge_kernel<<<grid, NTHREADS>>>(pred, all, B, C);

    int nparts = grid.x * grid.y;
    finish_kernel<<<1, NTHREADS>>>(out, nparts, B);
}

// round 3
// speedup vs baseline: 3.7351x; 3.7351x over previous
#include <cuda_runtime.h>
#include <cuda_bf16.h>
#include <math.h>
#include <stdint.h>

// ---------------------------------------------------------------------------
// PoincareEmbHingeLoss — mma.sync bf16 (HMMA) GEMM + fused arccosh/hinge.
// B=4096, C=10000 (padded to 10112), D=64.  Baseline-PTX only (no tcgen05).
// ---------------------------------------------------------------------------

#define D_DIM 64
#define BM 128
#define BN 128
#define NT 256
#define MARGIN 0.1f
#define BOUNDARY_EPS 1e-5f
#define ACOSH_EPS 1e-7f

#define MAX_B 4096
#define MAX_CP 10240
#define MAX_PARTIALS 4096

#define ROW_BYTES 144          // 64 bf16 = 128B, +16B pad -> conflict-free ldmatrix

__device__ __nv_bfloat16 g_pred_bf16[MAX_B * D_DIM];
__device__ __nv_bfloat16 g_all_bf16[MAX_CP * D_DIM];
__device__ float4 g_row_pack[MAX_B];    // {pn, 2/(1-pn), d2c+margin, 0}
__device__ float2 g_col_ania[MAX_CP];   // {an, 1/(1-an)}  (pad: {4e15, 1})
__device__ double g_partials[MAX_PARTIALS];

__device__ __forceinline__ uint32_t smem_u32(const void* p) {
    uint32_t a;
    asm("{ .reg .u64 t; cvta.to.shared.u64 t, %1; cvt.u32.u64 %0, t; }"
        : "=r"(a) : "l"(p));
    return a;
}

// ---------------------------------------------------------------------------
// Row prep: bf16 convert + pn, 2/(1-pn), d2c+margin (fp64 scalar path)
// ---------------------------------------------------------------------------
__global__ void prep_rows_kernel(const float* __restrict__ pred,
                                 const float* __restrict__ targ, int B) {
    int r = blockIdx.x * blockDim.x + threadIdx.x;
    if (r >= B) return;
    const float4* p4 = (const float4*)(pred + (size_t)r * D_DIM);
    const float4* t4 = (const float4*)(targ + (size_t)r * D_DIM);
    __nv_bfloat162* dst = (__nv_bfloat162*)(g_pred_bf16 + (size_t)r * D_DIM);
    float pn = 0.f, tn = 0.f, sc = 0.f;
#pragma unroll
    for (int i = 0; i < D_DIM / 4; i++) {
        float4 p = p4[i];
        float4 t = t4[i];
        pn += p.x * p.x + p.y * p.y + p.z * p.z + p.w * p.w;
        tn += t.x * t.x + t.y * t.y + t.z * t.z + t.w * t.w;
        float dx = p.x - t.x, dy = p.y - t.y, dz = p.z - t.z, dw = p.w - t.w;
        sc += dx * dx + dy * dy + dz * dz + dw * dw;
        dst[i * 2 + 0] = __floats2bfloat162_rn(p.x, p.y);
        dst[i * 2 + 1] = __floats2bfloat162_rn(p.z, p.w);
    }
    pn = fminf(fmaxf(pn, 0.f), 1.f - BOUNDARY_EPS);
    tn = fminf(fmaxf(tn, 0.f), 1.f - BOUNDARY_EPS);
    double x = 1.0 + 2.0 * (double)sc / ((1.0 - (double)pn) * (1.0 - (double)tn));
    double xm = 1.0 + (double)ACOSH_EPS;
    if (x < xm) x = xm;
    double d2c = log(x + sqrt(x * x - 1.0));
    g_row_pack[r] = make_float4(pn, 2.f / (1.f - pn), (float)d2c + MARGIN, 0.f);
}

// ---------------------------------------------------------------------------
// Col prep: bf16 convert (zero pad) + an, 1/(1-an) (pad self-masks via an=4e15)
// ---------------------------------------------------------------------------
__global__ void prep_cols_kernel(const float* __restrict__ all, int C, int CP) {
    int c = blockIdx.x * blockDim.x + threadIdx.x;
    if (c >= CP) return;
    __nv_bfloat162* dst = (__nv_bfloat162*)(g_all_bf16 + (size_t)c * D_DIM);
    if (c < C) {
        const float4* a4 = (const float4*)(all + (size_t)c * D_DIM);
        float an = 0.f;
#pragma unroll
        for (int i = 0; i < D_DIM / 4; i++) {
            float4 a = a4[i];
            an += a.x * a.x + a.y * a.y + a.z * a.z + a.w * a.w;
            dst[i * 2 + 0] = __floats2bfloat162_rn(a.x, a.y);
            dst[i * 2 + 1] = __floats2bfloat162_rn(a.z, a.w);
        }
        an = fminf(fmaxf(an, 0.f), 1.f - BOUNDARY_EPS);
        g_col_ania[c] = make_float2(an, 1.f / (1.f - an));
    } else {
        __nv_bfloat162 z = __floats2bfloat162_rn(0.f, 0.f);
#pragma unroll
        for (int i = 0; i < D_DIM / 2; i++) dst[i] = z;
        g_col_ania[c] = make_float2(4e15f, 1.f);  // forces hinge term to 0
    }
}

// ---------------------------------------------------------------------------
// Fused HMMA GEMM tile (128x128, K=64) + arccosh/hinge epilogue
// 8 warps = 4(m) x 2(n); warp tile 32x64; mma m16n8k16 bf16.
// ---------------------------------------------------------------------------
__global__ void __launch_bounds__(NT)
fused_mma_kernel(int B, int C) {
    __shared__ char smA[BM * ROW_BYTES];     // 18432
    __shared__ char smB[BN * ROW_BYTES];     // 18432
    __shared__ float2 smAnia[BN];            // 1024
    __shared__ float4 smRow[BM];             // 2048

    const int tid = threadIdx.x;
    const int lane = tid & 31;
    const int wid = tid >> 5;
    const int m0 = blockIdx.y * BM;
    const int n0 = blockIdx.x * BN;

    // ---- stage tiles ----
    const uint4* Ag = (const uint4*)(g_pred_bf16 + (size_t)m0 * D_DIM);
    const uint4* Bg = (const uint4*)(g_all_bf16 + (size_t)n0 * D_DIM);
#pragma unroll
    for (int i = 0; i < 4; i++) {
        int id = tid + i * NT;
        int r = id >> 3, c16 = id & 7;
        *(uint4*)(smA + r * ROW_BYTES + c16 * 16) = Ag[id];
        *(uint4*)(smB + r * ROW_BYTES + c16 * 16) = Bg[id];
    }
    if (tid < BN) smAnia[tid] = g_col_ania[n0 + tid];
    if (tid < BM) smRow[tid] = g_row_pack[m0 + tid];
    __syncthreads();

    const uint32_t sa = smem_u32(smA);
    const uint32_t sb = smem_u32(smB);
    const int wm = (wid & 3) * 32;      // warp row offset
    const int wn = (wid >> 2) * 64;     // warp col offset

    float acc[2][8][4];
#pragma unroll
    for (int mi = 0; mi < 2; mi++)
#pragma unroll
        for (int nj = 0; nj < 8; nj++)
#pragma unroll
            for (int e = 0; e < 4; e++) acc[mi][nj][e] = 0.f;

    // precomputed lane address components
    const uint32_t a_lane_off = (uint32_t)((lane & 15) * ROW_BYTES + (lane >> 4) * 16);
    const int bmat = lane >> 3, brim = lane & 7;
    const uint32_t b_lane_off =
        (uint32_t)(((bmat & 1) * 8 + brim) * ROW_BYTES + (bmat >> 1) * 16);

#pragma unroll
    for (int ks = 0; ks < 4; ks++) {
        uint32_t af[2][4];
#pragma unroll
        for (int mi = 0; mi < 2; mi++) {
            uint32_t addr = sa + (uint32_t)((wm + mi * 16) * ROW_BYTES + ks * 32) + a_lane_off;
            asm volatile("ldmatrix.sync.aligned.m8n8.x4.shared.b16 {%0,%1,%2,%3}, [%4];"
                         : "=r"(af[mi][0]), "=r"(af[mi][1]), "=r"(af[mi][2]), "=r"(af[mi][3])
                         : "r"(addr));
        }
        uint32_t bf[8][2];
#pragma unroll
        for (int g = 0; g < 4; g++) {
            uint32_t addr = sb + (uint32_t)((wn + g * 16) * ROW_BYTES + ks * 32) + b_lane_off;
            uint32_t r0, r1, r2, r3;
            asm volatile("ldmatrix.sync.aligned.m8n8.x4.shared.b16 {%0,%1,%2,%3}, [%4];"
                         : "=r"(r0), "=r"(r1), "=r"(r2), "=r"(r3)
                         : "r"(addr));
            bf[2 * g + 0][0] = r0; bf[2 * g + 0][1] = r2;
            bf[2 * g + 1][0] = r1; bf[2 * g + 1][1] = r3;
        }
#pragma unroll
        for (int mi = 0; mi < 2; mi++)
#pragma unroll
            for (int nj = 0; nj < 8; nj++)
                asm volatile(
                    "mma.sync.aligned.m16n8k16.row.col.f32.bf16.bf16.f32 "
                    "{%0,%1,%2,%3}, {%4,%5,%6,%7}, {%8,%9}, {%0,%1,%2,%3};"
                    : "+f"(acc[mi][nj][0]), "+f"(acc[mi][nj][1]),
                      "+f"(acc[mi][nj][2]), "+f"(acc[mi][nj][3])
                    : "r"(af[mi][0]), "r"(af[mi][1]), "r"(af[mi][2]), "r"(af[mi][3]),
                      "r"(bf[nj][0]), "r"(bf[nj][1]));
    }

    // ---- epilogue ----
    const int gid = lane >> 2, tig = lane & 3;
    float tsum = 0.f;
#pragma unroll
    for (int mi = 0; mi < 2; mi++) {
        float4 rp0 = smRow[wm + mi * 16 + gid];
        float4 rp1 = smRow[wm + mi * 16 + gid + 8];
#pragma unroll
        for (int nj = 0; nj < 8; nj++) {
            int c0 = wn + nj * 8 + tig * 2;
            float2 a0 = smAnia[c0];
            float2 a1 = smAnia[c0 + 1];
#pragma unroll
            for (int e = 0; e < 4; e++) {
                const float4& rp = (e < 2) ? rp0 : rp1;
                const float2& ai = (e & 1) ? a1 : a0;
                float q = fmaf(-2.f, acc[mi][nj][e], rp.x + ai.x);
                float t = fmaxf(q * (rp.y * ai.y), ACOSH_EPS);
                float w = t * (t + 2.f);
                float s;
                asm("sqrt.approx.f32 %0, %1;" : "=f"(s) : "f"(w));
                float dw = __logf(1.f + t + s);   // arccosh(1+t)
                tsum += fmaxf(rp.z - dw, 0.f);
            }
        }
    }

    // ---- deterministic block reduce (reuse A tile) ----
    __syncthreads();
    float* red = (float*)smA;
    red[tid] = tsum;
    __syncthreads();
#pragma unroll
    for (int s = NT / 2; s > 0; s >>= 1) {
        if (tid < s) red[tid] += red[tid + s];
        __syncthreads();
    }
    if (tid == 0)
        g_partials[blockIdx.y * gridDim.x + blockIdx.x] = (double)red[0];
}

// ---------------------------------------------------------------------------
__global__ void finish_kernel(float* __restrict__ out, int nparts, int B) {
    __shared__ double red[NT];
    int tid = threadIdx.x;
    double s = 0.0;
    for (int i = tid; i < nparts; i += NT) s += g_partials[i];
    red[tid] = s;
    __syncthreads();
#pragma unroll
    for (int st = NT / 2; st > 0; st >>= 1) {
        if (tid < st) red[tid] += red[tid + st];
        __syncthreads();
    }
    if (tid == 0)
        out[0] = (float)((red[0] - (double)MARGIN * (double)B) / (double)B);
}

// ---------------------------------------------------------------------------
extern "C" void kernel_launch(void* const* d_in, const int* in_sizes, int n_in,
                              void* d_out, int out_size) {
    const float* pred = (const float*)d_in[0];
    const float* targ = (const float*)d_in[1];
    const float* all  = (const float*)d_in[2];
    float* out = (float*)d_out;

    int B = in_sizes[0] / D_DIM;               // 4096
    int C = in_sizes[2] / D_DIM;               // 10000
    int ctiles = (C + BN - 1) / BN;            // 79
    int CP = ctiles * BN;                      // 10112
    int rtiles = B / BM;                       // 32

    prep_rows_kernel<<<(B + 127) / 128, 128>>>(pred, targ, B);
    prep_cols_kernel<<<(CP + 127) / 128, 128>>>(all, C, CP);

    dim3 grid(ctiles, rtiles);                 // (79, 32) = 2528 tiles
    fused_mma_kernel<<<grid, NT>>>(B, C);

    finish_kernel<<<1, NT>>>(out, ctiles * rtiles, B);
}

// round 5
// speedup vs baseline: 4.1482x; 1.1106x over previous
#include <cuda_runtime.h>
#include <cuda_bf16.h>
#include <math.h>
#include <stdint.h>

// ---------------------------------------------------------------------------
// PoincareEmbHingeLoss — HMMA bf16 GEMM + fused hinge epilogue with
// per-row activity threshold (t < T = cosh(dm)-1) and log-of-product trick.
// B=4096, C=10000 (padded 10112), D=64.
// ---------------------------------------------------------------------------

#define D_DIM 64
#define BM 128
#define BN 128
#define NT 256
#define MARGIN 0.1f
#define BOUNDARY_EPS 1e-5f
#define ACOSH_EPS 1e-7f
#define LN2F 0.69314718056f

#define MAX_B 4096
#define MAX_CP 10240
#define MAX_PARTIALS 4096

#define ROW_BYTES 144          // 64 bf16 = 128B, +16B pad -> conflict-free ldmatrix

__device__ __nv_bfloat16 g_pred_bf16[MAX_B * D_DIM];
__device__ __nv_bfloat16 g_all_bf16[MAX_CP * D_DIM];
__device__ float4 g_row_pack[MAX_B];    // {pn, 2/(1-pn), dm=d2c+margin, T=cosh(dm)-1}
__device__ float2 g_col_ania[MAX_CP];   // {an, 1/(1-an)}  (pad: {4e15, 1})
__device__ double g_partials[MAX_PARTIALS];

__device__ __forceinline__ uint32_t smem_u32(const void* p) {
    uint32_t a;
    asm("{ .reg .u64 t; cvta.to.shared.u64 t, %1; cvt.u32.u64 %0, t; }"
        : "=r"(a) : "l"(p));
    return a;
}

// ---------------------------------------------------------------------------
// Combined prep: rows (bf16 + pn/rs/dm/T, fp64 scalar path) and cols (bf16 + an/ia)
// ---------------------------------------------------------------------------
__global__ void prep_kernel(const float* __restrict__ pred,
                            const float* __restrict__ targ,
                            const float* __restrict__ all,
                            int B, int C, int CP) {
    int idx = blockIdx.x * blockDim.x + threadIdx.x;

    if (idx < B) {
        const float4* p4 = (const float4*)(pred + (size_t)idx * D_DIM);
        const float4* t4 = (const float4*)(targ + (size_t)idx * D_DIM);
        __nv_bfloat162* dst = (__nv_bfloat162*)(g_pred_bf16 + (size_t)idx * D_DIM);
        float pn = 0.f, tn = 0.f, sc = 0.f;
#pragma unroll
        for (int i = 0; i < D_DIM / 4; i++) {
            float4 p = p4[i];
            float4 t = t4[i];
            pn += p.x * p.x + p.y * p.y + p.z * p.z + p.w * p.w;
            tn += t.x * t.x + t.y * t.y + t.z * t.z + t.w * t.w;
            float dx = p.x - t.x, dy = p.y - t.y, dz = p.z - t.z, dw = p.w - t.w;
            sc += dx * dx + dy * dy + dz * dz + dw * dw;
            dst[i * 2 + 0] = __floats2bfloat162_rn(p.x, p.y);
            dst[i * 2 + 1] = __floats2bfloat162_rn(p.z, p.w);
        }
        pn = fminf(fmaxf(pn, 0.f), 1.f - BOUNDARY_EPS);
        tn = fminf(fmaxf(tn, 0.f), 1.f - BOUNDARY_EPS);
        double x = 1.0 + 2.0 * (double)sc / ((1.0 - (double)pn) * (1.0 - (double)tn));
        double xm = 1.0 + (double)ACOSH_EPS;
        if (x < xm) x = xm;
        double d2c = log(x + sqrt(x * x - 1.0));
        double dm = d2c + (double)MARGIN;
        double T = cosh(dm) - 1.0;   // activity threshold on t
        g_row_pack[idx] = make_float4(pn, 2.f / (1.f - pn), (float)dm, (float)T);
    }

    if (idx < CP) {
        __nv_bfloat162* dst = (__nv_bfloat162*)(g_all_bf16 + (size_t)idx * D_DIM);
        if (idx < C) {
            const float4* a4 = (const float4*)(all + (size_t)idx * D_DIM);
            float an = 0.f;
#pragma unroll
            for (int i = 0; i < D_DIM / 4; i++) {
                float4 a = a4[i];
                an += a.x * a.x + a.y * a.y + a.z * a.z + a.w * a.w;
                dst[i * 2 + 0] = __floats2bfloat162_rn(a.x, a.y);
                dst[i * 2 + 1] = __floats2bfloat162_rn(a.z, a.w);
            }
            an = fminf(fmaxf(an, 0.f), 1.f - BOUNDARY_EPS);
            g_col_ania[idx] = make_float2(an, 1.f / (1.f - an));
        } else {
            __nv_bfloat162 z = __floats2bfloat162_rn(0.f, 0.f);
#pragma unroll
            for (int i = 0; i < D_DIM / 2; i++) dst[i] = z;
            g_col_ania[idx] = make_float2(4e15f, 1.f);  // t huge -> inactive -> 0
        }
    }
}

// ---------------------------------------------------------------------------
// Fused HMMA GEMM tile (128x128, K=64) + threshold/log-product epilogue
// 8 warps = 4(m) x 2(n); warp tile 32x64; mma m16n8k16 bf16.
// ---------------------------------------------------------------------------
__global__ void __launch_bounds__(NT, 2)
fused_mma_kernel(int B, int C) {
    __shared__ char smA[BM * ROW_BYTES];     // 18432
    __shared__ char smB[BN * ROW_BYTES];     // 18432
    __shared__ float2 smAnia[BN];            // 1024
    __shared__ float4 smRow[BM];             // 2048
    __shared__ float smRed[8];

    const int tid = threadIdx.x;
    const int lane = tid & 31;
    const int wid = tid >> 5;
    const int m0 = blockIdx.y * BM;
    const int n0 = blockIdx.x * BN;

    // ---- stage tiles ----
    const uint4* Ag = (const uint4*)(g_pred_bf16 + (size_t)m0 * D_DIM);
    const uint4* Bg = (const uint4*)(g_all_bf16 + (size_t)n0 * D_DIM);
#pragma unroll
    for (int i = 0; i < 4; i++) {
        int id = tid + i * NT;
        int r = id >> 3, c16 = id & 7;
        *(uint4*)(smA + r * ROW_BYTES + c16 * 16) = Ag[id];
        *(uint4*)(smB + r * ROW_BYTES + c16 * 16) = Bg[id];
    }
    if (tid < BN) smAnia[tid] = g_col_ania[n0 + tid];
    if (tid < BM) smRow[tid] = g_row_pack[m0 + tid];
    __syncthreads();

    const uint32_t sa = smem_u32(smA);
    const uint32_t sb = smem_u32(smB);
    const int wm = (wid & 3) * 32;      // warp row offset
    const int wn = (wid >> 2) * 64;     // warp col offset

    float acc[2][8][4];
#pragma unroll
    for (int mi = 0; mi < 2; mi++)
#pragma unroll
        for (int nj = 0; nj < 8; nj++)
#pragma unroll
            for (int e = 0; e < 4; e++) acc[mi][nj][e] = 0.f;

    const uint32_t a_lane_off = (uint32_t)((lane & 15) * ROW_BYTES + (lane >> 4) * 16);
    const int bmat = lane >> 3, brim = lane & 7;
    const uint32_t b_lane_off =
        (uint32_t)(((bmat & 1) * 8 + brim) * ROW_BYTES + (bmat >> 1) * 16);

#pragma unroll
    for (int ks = 0; ks < 4; ks++) {
        uint32_t af[2][4];
#pragma unroll
        for (int mi = 0; mi < 2; mi++) {
            uint32_t addr = sa + (uint32_t)((wm + mi * 16) * ROW_BYTES + ks * 32) + a_lane_off;
            asm volatile("ldmatrix.sync.aligned.m8n8.x4.shared.b16 {%0,%1,%2,%3}, [%4];"
                         : "=r"(af[mi][0]), "=r"(af[mi][1]), "=r"(af[mi][2]), "=r"(af[mi][3])
                         : "r"(addr));
        }
        uint32_t bfr[8][2];
#pragma unroll
        for (int g = 0; g < 4; g++) {
            uint32_t addr = sb + (uint32_t)((wn + g * 16) * ROW_BYTES + ks * 32) + b_lane_off;
            uint32_t r0, r1, r2, r3;
            asm volatile("ldmatrix.sync.aligned.m8n8.x4.shared.b16 {%0,%1,%2,%3}, [%4];"
                         : "=r"(r0), "=r"(r1), "=r"(r2), "=r"(r3)
                         : "r"(addr));
            bfr[2 * g + 0][0] = r0; bfr[2 * g + 0][1] = r2;
            bfr[2 * g + 1][0] = r1; bfr[2 * g + 1][1] = r3;
        }
#pragma unroll
        for (int mi = 0; mi < 2; mi++)
#pragma unroll
            for (int nj = 0; nj < 8; nj++)
                asm volatile(
                    "mma.sync.aligned.m16n8k16.row.col.f32.bf16.bf16.f32 "
                    "{%0,%1,%2,%3}, {%4,%5,%6,%7}, {%8,%9}, {%0,%1,%2,%3};"
                    : "+f"(acc[mi][nj][0]), "+f"(acc[mi][nj][1]),
                      "+f"(acc[mi][nj][2]), "+f"(acc[mi][nj][3])
                    : "r"(af[mi][0]), "r"(af[mi][1]), "r"(af[mi][2]), "r"(af[mi][3]),
                      "r"(bfr[nj][0]), "r"(bfr[nj][1]));
    }

    // ---- epilogue: threshold + log-of-product (1 sqrt/elem, 1 lg2 / 8 elems) ----
    const int gid = lane >> 2, tig = lane & 3;
    float4 rp[4];                     // [mi*2 + rowhalf]
    rp[0] = smRow[wm + gid];
    rp[1] = smRow[wm + gid + 8];
    rp[2] = smRow[wm + 16 + gid];
    rp[3] = smRow[wm + 16 + gid + 8];

    float cnt[4] = {0.f, 0.f, 0.f, 0.f};
    float logsum = 0.f;

#pragma unroll
    for (int njp = 0; njp < 4; njp++) {
        int c0 = wn + njp * 16 + tig * 2;
        float2 ca[4];
        ca[0] = smAnia[c0];
        ca[1] = smAnia[c0 + 1];
        ca[2] = smAnia[c0 + 8];
        ca[3] = smAnia[c0 + 9];
#pragma unroll
        for (int mi = 0; mi < 2; mi++) {
            float prod = 1.f;
#pragma unroll
            for (int jj = 0; jj < 2; jj++) {
#pragma unroll
                for (int e = 0; e < 4; e++) {
                    float acv = acc[mi][2 * njp + jj][e];
                    const float4& r = rp[mi * 2 + (e >> 1)];
                    const float2& c = ca[jj * 2 + (e & 1)];
                    float q = fmaf(-2.f, acv, r.x + c.x);
                    float t = fmaxf(q * (r.y * c.y), ACOSH_EPS);
                    bool act = t < r.w;                    // active iff t < cosh(dm)-1
                    float w = fmaf(t, t, t + t);           // t^2 + 2t
                    float s;
                    asm("sqrt.approx.f32 %0, %1;" : "=f"(s) : "f"(w));
                    float y = act ? (1.f + t + s) : 1.f;   // y = exp(dw) if active
                    prod *= y;
                    cnt[mi * 2 + (e >> 1)] += act ? 1.f : 0.f;
                }
            }
            float l;
            asm("lg2.approx.f32 %0, %1;" : "=f"(l) : "f"(prod));
            logsum += l;
        }
    }

    float tsum = fmaf(-LN2F, logsum, 0.f);
#pragma unroll
    for (int i = 0; i < 4; i++) tsum = fmaf(cnt[i], rp[i].z, tsum);

    // ---- warp-shuffle reduce, then cross-warp via smem ----
#pragma unroll
    for (int o = 16; o > 0; o >>= 1)
        tsum += __shfl_xor_sync(0xFFFFFFFFu, tsum, o);
    if (lane == 0) smRed[wid] = tsum;
    __syncthreads();
    if (tid == 0) {
        float s = 0.f;
#pragma unroll
        for (int i = 0; i < 8; i++) s += smRed[i];
        g_partials[blockIdx.y * gridDim.x + blockIdx.x] = (double)s;
    }
}

// ---------------------------------------------------------------------------
__global__ void finish_kernel(float* __restrict__ out, int nparts, int B) {
    __shared__ double red[512];
    int tid = threadIdx.x;
    double s = 0.0;
    for (int i = tid; i < nparts; i += 512) s += g_partials[i];
    red[tid] = s;
    __syncthreads();
#pragma unroll
    for (int st = 256; st > 0; st >>= 1) {
        if (tid < st) red[tid] += red[tid + st];
        __syncthreads();
    }
    if (tid == 0)
        out[0] = (float)((red[0] - (double)MARGIN * (double)B) / (double)B);
}

// ---------------------------------------------------------------------------
extern "C" void kernel_launch(void* const* d_in, const int* in_sizes, int n_in,
                              void* d_out, int out_size) {
    const float* pred = (const float*)d_in[0];
    const float* targ = (const float*)d_in[1];
    const float* all  = (const float*)d_in[2];
    float* out = (float*)d_out;

    int B = in_sizes[0] / D_DIM;               // 4096
    int C = in_sizes[2] / D_DIM;               // 10000
    int ctiles = (C + BN - 1) / BN;            // 79
    int CP = ctiles * BN;                      // 10112
    int rtiles = B / BM;                       // 32

    int mx = (CP > B) ? CP : B;
    prep_kernel<<<(mx + 127) / 128, 128>>>(pred, targ, all, B, C, CP);

    dim3 grid(ctiles, rtiles);                 // (79, 32) = 2528 tiles
    fused_mma_kernel<<<grid, NT>>>(B, C);

    finish_kernel<<<1, 512>>>(out, ctiles * rtiles, B);
}